// round 1
// baseline (speedup 1.0000x reference)
#include <cuda_runtime.h>

#define NN 1024
#define LL 64

// scratch (allocation-free rule: device globals)
__device__ float g_preib[NN * LL];   // pre_i + be1
__device__ float g_prej [NN * LL];   // pre_j
__device__ float g_V    [NN];
__device__ float g_newH [NN * LL];

// fast, accurate-enough tanh: 1 - 2/(exp(2x)+1)
// handles +/-inf saturation correctly (exp->inf => 1, exp->0 => -1)
__device__ __forceinline__ float ftanh(float x) {
    float e = __expf(2.0f * x);
    return 1.0f - __fdividef(2.0f, e + 1.0f);
}

// ---------------------------------------------------------------------------
// Kernel A: H = LM[cat]; preib = H @ We1[:L] + be1 ; prej = H @ We1[L:2L]
// ---------------------------------------------------------------------------
__global__ void prep_kernel(const int* __restrict__ cats,
                            const float* __restrict__ LM,
                            const float* __restrict__ We1,
                            const float* __restrict__ be1) {
    __shared__ float Hs[LL];
    int n = blockIdx.x, l = threadIdx.x;
    Hs[l] = LM[cats[n] * LL + l];
    __syncthreads();
    float ai = be1[l], aj = 0.0f;
#pragma unroll
    for (int k = 0; k < LL; k++) {
        float h = Hs[k];
        ai = fmaf(h, We1[k * LL + l], ai);
        aj = fmaf(h, We1[(LL + k) * LL + l], aj);
    }
    g_preib[n * LL + l] = ai;
    g_prej[n * LL + l] = aj;
}

// ---------------------------------------------------------------------------
// Kernel B: the O(N^2 * L^2) pair loop.
// Block = atom i (1024 blocks). 8 warps; each warp streams j = warp, warp+8, ...
// Per pair: h1 (64 vals, tanh) -> smem (double buffered, warp-private),
// 64x64 matvec with We2 columns held in registers (2 cols per lane, float2),
// tanh, accumulate V. j == i excluded (total - diag).
// ---------------------------------------------------------------------------
__global__ __launch_bounds__(256, 1)
void pair_kernel(const float* __restrict__ coords,
                 const float* __restrict__ We1,
                 const float* __restrict__ We2,
                 const float* __restrict__ be2) {
    __shared__ float s_preib[LL];
    __shared__ float s_w1z[LL];
    __shared__ __align__(16) float s_h1[8][2][LL];
    __shared__ float s_red[8];

    const int i = blockIdx.x;
    const int t = threadIdx.x;
    const int w = t >> 5, lane = t & 31;

    // We2 columns 2*lane, 2*lane+1 in registers (128 regs)
    float2 wv[LL];
#pragma unroll
    for (int k = 0; k < LL; k++)
        wv[k] = *reinterpret_cast<const float2*>(&We2[k * LL + 2 * lane]);
    const float be2a = be2[2 * lane];
    const float be2b = be2[2 * lane + 1];

    if (t < LL) {
        s_preib[t] = g_preib[i * LL + t];
        s_w1z[t]   = We1[2 * LL * LL + t];   // w1z = We1 row 128
    }
    const float zx = coords[3 * i], zy = coords[3 * i + 1], zz = coords[3 * i + 2];
    __syncthreads();

    const float pA  = s_preib[lane],      pB  = s_preib[lane + 32];
    const float wzA = s_w1z[lane],        wzB = s_w1z[lane + 32];

    float vpart = 0.0f;
    int buf = 0;

    for (int j = w; j < NN; j += 8) {
        // phase 1: h1 (lane covers k = lane and k = lane+32)
        float dx = zx - coords[3 * j];
        float dy = zy - coords[3 * j + 1];
        float dz = zz - coords[3 * j + 2];
        float d2 = dx * dx + dy * dy + dz * dz;
        float s0 = pA + g_prej[j * LL + lane]      + d2 * wzA;
        float s1 = pB + g_prej[j * LL + 32 + lane] + d2 * wzB;
        s_h1[w][buf][lane]      = ftanh(s0);
        s_h1[w][buf][lane + 32] = ftanh(s1);
        __syncwarp();

        // phase 2: y = tanh(h1 @ We2 + be2); accumulate sum over l
        float a0 = 0.f, a1 = 0.f, b0 = 0.f, b1 = 0.f;
#pragma unroll
        for (int k = 0; k < LL; k += 4) {
            float4 h = *reinterpret_cast<const float4*>(&s_h1[w][buf][k]);
            a0 = fmaf(h.x, wv[k].x,     a0);
            b0 = fmaf(h.x, wv[k].y,     b0);
            a1 = fmaf(h.y, wv[k + 1].x, a1);
            b1 = fmaf(h.y, wv[k + 1].y, b1);
            a0 = fmaf(h.z, wv[k + 2].x, a0);
            b0 = fmaf(h.z, wv[k + 2].y, b0);
            a1 = fmaf(h.w, wv[k + 3].x, a1);
            b1 = fmaf(h.w, wv[k + 3].y, b1);
        }
        if (j != i)
            vpart += ftanh(a0 + a1 + be2a) + ftanh(b0 + b1 + be2b);
        buf ^= 1;
    }

    // reduce V over warp + block
#pragma unroll
    for (int o = 16; o > 0; o >>= 1)
        vpart += __shfl_down_sync(0xffffffffu, vpart, o);
    if (lane == 0) s_red[w] = vpart;
    __syncthreads();
    if (t == 0) {
        float v = 0.f;
#pragma unroll
        for (int q = 0; q < 8; q++) v += s_red[q];
        g_V[i] = v;
    }
}

// ---------------------------------------------------------------------------
// Kernel C1: hh = tanh(H@Wh1[:L] + V*Wh1[L] + bh1); newH = tanh(hh@Wh2 + bh2)
// ---------------------------------------------------------------------------
__global__ void head_kernel(const int* __restrict__ cats,
                            const float* __restrict__ LM,
                            const float* __restrict__ Wh1,
                            const float* __restrict__ bh1,
                            const float* __restrict__ Wh2,
                            const float* __restrict__ bh2) {
    __shared__ float Hs[LL];
    __shared__ float hhs[LL];
    int n = blockIdx.x, l = threadIdx.x;
    Hs[l] = LM[cats[n] * LL + l];
    __syncthreads();
    float V = g_V[n];
    float acc = fmaf(V, Wh1[LL * LL + l], bh1[l]);   // Wh1 row L
#pragma unroll
    for (int k = 0; k < LL; k++)
        acc = fmaf(Hs[k], Wh1[k * LL + l], acc);
    hhs[l] = tanhf(acc);
    __syncthreads();
    float acc2 = bh2[l];
#pragma unroll
    for (int k = 0; k < LL; k++)
        acc2 = fmaf(hhs[k], Wh2[k * LL + l], acc2);
    g_newH[n * LL + l] = tanhf(acc2);
}

// ---------------------------------------------------------------------------
// Kernel C2: Hsum = sum_n newH; out = Hsum @ Wo + bo
// ---------------------------------------------------------------------------
__global__ void final_kernel(const float* __restrict__ Wo,
                             const float* __restrict__ bo,
                             float* __restrict__ out) {
    __shared__ float s[256];
    int t = threadIdx.x;
    int l = t & 63, r = t >> 6;
    float acc = 0.f;
    for (int n = r; n < NN; n += 4)
        acc += g_newH[n * LL + l];
    s[t] = acc;
    __syncthreads();
    if (t < 64) {
        float hs = s[t] + s[t + 64] + s[t + 128] + s[t + 192];
        s[t] = hs * Wo[t];
    }
    __syncthreads();
    if (t == 0) {
        float o = bo[0];
#pragma unroll
        for (int q = 0; q < 64; q++) o += s[q];
        out[0] = o;
    }
}

// ---------------------------------------------------------------------------
extern "C" void kernel_launch(void* const* d_in, const int* in_sizes, int n_in,
                              void* d_out, int out_size) {
    (void)in_sizes; (void)n_in; (void)out_size;
    const int*   cats   = (const int*)  d_in[0];
    const float* coords = (const float*)d_in[1];
    const float* LM     = (const float*)d_in[2];
    const float* We1    = (const float*)d_in[3];
    const float* be1    = (const float*)d_in[4];
    const float* We2    = (const float*)d_in[5];
    const float* be2    = (const float*)d_in[6];
    const float* Wh1    = (const float*)d_in[7];
    const float* bh1    = (const float*)d_in[8];
    const float* Wh2    = (const float*)d_in[9];
    const float* bh2    = (const float*)d_in[10];
    const float* Wo     = (const float*)d_in[11];
    const float* bo     = (const float*)d_in[12];

    prep_kernel <<<NN, LL >>>(cats, LM, We1, be1);
    pair_kernel <<<NN, 256>>>(coords, We1, We2, be2);
    head_kernel <<<NN, LL >>>(cats, LM, Wh1, bh1, Wh2, bh2);
    final_kernel<<<1,  256>>>(Wo, bo, (float*)d_out);
}